// round 15
// baseline (speedup 1.0000x reference)
#include <cuda_runtime.h>
#include <cuda_bf16.h>
#include <cstdint>
#include <cmath>

#define T_LEN 1024
#define NH    512
#define NI    128
#define BSZ   64
#define DT_C  0.1f

// Hoisted input projection scratch: tanh(x @ x2h), [B, T, H] fp32 (134 MB).
__device__ float g_tanhI[(size_t)BSZ * T_LEN * NH];

typedef unsigned long long ull;

// ---------------------------------------------------------------------------
// helpers
// ---------------------------------------------------------------------------
__device__ __forceinline__ uint32_t smem_u32(const void* p) {
    uint32_t a;
    asm("{ .reg .u64 t; cvta.to.shared.u64 t, %1; cvt.u32.u64 %0, t; }" : "=r"(a) : "l"(p));
    return a;
}
__device__ __forceinline__ uint32_t mapa_sc(uint32_t addr, uint32_t rank) {
    uint32_t r;
    asm("mapa.shared::cluster.u32 %0, %1, %2;" : "=r"(r) : "r"(addr), "r"(rank));
    return r;
}
__device__ __forceinline__ void cluster_sync_() {
    asm volatile("barrier.cluster.arrive.aligned;" ::: "memory");
    asm volatile("barrier.cluster.wait.aligned;" ::: "memory");
}
__device__ __forceinline__ ull pack2(float w) {
    ull r;
    asm("mov.b64 %0, {%1, %1};" : "=l"(r) : "f"(w));
    return r;
}
__device__ __forceinline__ void unpack2(float& lo, float& hi, ull v) {
    asm("mov.b64 {%0, %1}, %2;" : "=f"(lo), "=f"(hi) : "l"(v));
}
__device__ __forceinline__ void ffma2(ull& d, ull a, ull b) {
    asm("fma.rn.f32x2 %0, %1, %2, %0;" : "+l"(d) : "l"(a), "l"(b));
}
__device__ __forceinline__ void mbar_init(uint32_t addr, uint32_t count) {
    asm volatile("mbarrier.init.shared.b64 [%0], %1;" :: "r"(addr), "r"(count) : "memory");
}
__device__ __forceinline__ void mbar_expect(uint32_t addr, uint32_t bytes) {
    asm volatile("mbarrier.arrive.expect_tx.shared.b64 _, [%0], %1;"
                 :: "r"(addr), "r"(bytes) : "memory");
}
__device__ __forceinline__ void mbar_wait(uint32_t mbar, uint32_t parity) {
    uint32_t done;
    asm volatile(
        "{\n\t.reg .pred p;\n\t"
        "mbarrier.try_wait.parity.acquire.cluster.shared::cta.b64 p, [%1], %2;\n\t"
        "selp.b32 %0, 1, 0, p;\n\t}"
        : "=r"(done) : "r"(mbar), "r"(parity) : "memory");
    if (!done) {
        asm volatile(
            "{\n\t.reg .pred P1;\n\t"
            "W_%=:\n\t"
            "mbarrier.try_wait.parity.acquire.cluster.shared::cta.b64 P1, [%0], %1, 0x989680;\n\t"
            "@P1 bra.uni D_%=;\n\t"
            "bra.uni W_%=;\n\t"
            "D_%=:\n\t}"
            :: "r"(mbar), "r"(parity) : "memory");
    }
}
__device__ __forceinline__ void fence_async_() {
    asm volatile("fence.proxy.async.shared::cta;" ::: "memory");
}
__device__ __forceinline__ void bulk_dsm(uint32_t dst_cluster, uint32_t src_cta,
                                         uint32_t bytes, uint32_t mbar_cluster) {
    asm volatile(
        "cp.async.bulk.shared::cluster.shared::cta.mbarrier::complete_tx::bytes "
        "[%0], [%1], %2, [%3];"
        :: "r"(dst_cluster), "r"(src_cta), "r"(bytes), "r"(mbar_cluster) : "memory");
}

// ---------------------------------------------------------------------------
// Phase 1: g_tanhI[bt, h] = tanh( x[bt, :] @ x2h[:, h] )
// ---------------------------------------------------------------------------
__global__ void __launch_bounds__(256) phase1_kernel(const float* __restrict__ x,
                                                     const float* __restrict__ x2h) {
    __shared__ float  x_s[16 * 132];
    __shared__ float4 w4_s[128 * 16];
    const int tid = threadIdx.x;
    const int bt0 = blockIdx.x * 16;

    for (int i = tid; i < 512; i += 256) {
        int r = i >> 5, c = i & 31;
        float4 v = *reinterpret_cast<const float4*>(x + (size_t)(bt0 + r) * NI + c * 4);
        *reinterpret_cast<float4*>(x_s + r * 132 + c * 4) = v;
    }

    const int tt = tid & 15;
    const int jc = tid >> 4;
    for (int chunk = 0; chunk < 8; ++chunk) {
        __syncthreads();
        const int jbase = chunk * 64;
        for (int i = tid; i < 2048; i += 256) {
            int k = i >> 4, jq = i & 15;
            w4_s[k * 16 + jq] =
                *reinterpret_cast<const float4*>(x2h + (size_t)k * NH + jbase + jq * 4);
        }
        __syncthreads();
        float a0 = 0.f, a1 = 0.f, a2 = 0.f, a3 = 0.f;
        #pragma unroll 8
        for (int k = 0; k < 128; ++k) {
            float  xv = x_s[tt * 132 + k];
            float4 w  = w4_s[k * 16 + jc];
            a0 = fmaf(xv, w.x, a0); a1 = fmaf(xv, w.y, a1);
            a2 = fmaf(xv, w.z, a2); a3 = fmaf(xv, w.w, a3);
        }
        float4 o = make_float4(tanhf(a0), tanhf(a1), tanhf(a2), tanhf(a3));
        *reinterpret_cast<float4*>(g_tanhI + (size_t)(bt0 + tt) * NH + jbase + jc * 4) = o;
    }
}

// ---------------------------------------------------------------------------
// Phase 2: recurrence. 16 clusters x 8 CTAs x 512 threads (R14 machinery).
// k-pair packed math everywhere: GEMM1 weights pre-packed in registers
// (zero movs), hy rank-blocked [r][m][kl], GEMM2 k-pair with duplicated pre.
//
// SMEM float layout:
//   [0)      wT      64*514 = 32896   (w[j][k], EVEN stride for LDS.64 pairs)
//   [32896)  hyb     8*4*64 = 2048    ([rank][m][kl]; 1KB blocks)
//   [34944)  pd      256 ull = 512    (pre dup [j][m] = {p,p})
//   [35456)  stage   8*64*4 = 2048    ([ks][jg][m] scalars)
//   [37504)  red     8*4*64 = 2048    ([src][m][kl]; 1KB blocks)
//   [39552)  rdo     8*4*64 = 2048    (local staging [tgt][m][kl])
//   [41600)  hyst    4*64   = 256     ([m][kl])
//   [41856)  bias    64
//   [41920)  mbars   red(8B) + hy(8B) = 4 floats
//   total 41924 floats = 167696 B
// ---------------------------------------------------------------------------
#define WS        514
#define W_OFF     0
#define HYB_OFF   32896
#define PD_OFF    34944
#define STG_OFF   35456
#define RED_OFF   37504
#define RDO_OFF   39552
#define HYST_OFF  41600
#define BIAS_OFF  41856
#define MBAR_OFF  41920
#define SMEM_FLOATS 41924
#define SMEM_BYTES  (SMEM_FLOATS * 4)

__global__ void __launch_bounds__(512)
rnn_kernel(const float* __restrict__ h2h, const float* __restrict__ bias,
           const float* __restrict__ gamma_v, const float* __restrict__ eps_v,
           float* __restrict__ out_states, float* __restrict__ out_hy) {
    extern __shared__ float sm[];
    float* bias_s = sm + BIAS_OFF;
    ull*   pd64   = reinterpret_cast<ull*>(sm + PD_OFF);

    const int tid = threadIdx.x;
    uint32_t rank;
    asm("mov.u32 %0, %%cluster_ctarank;" : "=r"(rank));
    const int m_base = (blockIdx.x >> 3) * 4;
    const int J0 = (int)rank * 64;
    const uint32_t smb = smem_u32(sm);
    const uint32_t red_mbar = smb + MBAR_OFF * 4;
    const uint32_t hy_mbar  = smb + MBAR_OFF * 4 + 8;

    // --- init: weights (even stride), bias, zero hyb, mbars + phase-0 arms ---
    for (int idx = tid; idx < 64 * 512; idx += 512) {
        int k = idx >> 6, jl = idx & 63;
        sm[W_OFF + jl * WS + k] = h2h[(size_t)k * NH + J0 + jl];
    }
    if (tid < 64) bias_s[tid] = bias[J0 + tid];
    for (int i = tid; i < 2048; i += 512) sm[HYB_OFF + i] = 0.f;
    if (tid == 0) {
        mbar_init(red_mbar, 1);
        mbar_init(hy_mbar, 1);
        mbar_expect(red_mbar, 7168);   // 7 peers x 1KB, phase 0
        mbar_expect(hy_mbar, 7168);
    }

    // --- thread mappings ---
    const int ks = tid >> 6;          // GEMM1 k-chunk 0..7 (= hyb rank-block)
    const int jg = tid & 63;          // GEMM1 local j
    const int kp = tid >> 1;          // GEMM2 k-pair 0..255
    const int mh = tid & 1;           // GEMM2 m-half
    const int m_u  = tid >> 6;        // update (tid<256): [m][kl]
    const int kl_u = tid & 63;
    const int k_own = J0 + kl_u;

    // bulk issuers: threads 256..262, peer p = (rank + 1 + (tid-256)) & 7
    const bool issuer = (tid >= 256 && tid < 263);
    uint32_t red_dst = 0, red_src = 0, red_mb = 0;
    uint32_t hy_dst = 0, hy_src = 0, hy_mb = 0;
    if (issuer) {
        const uint32_t p = (rank + 1u + (uint32_t)(tid - 256)) & 7u;
        red_dst = mapa_sc(smb + RED_OFF * 4, p) + rank * 1024;
        red_src = smb + RDO_OFF * 4 + p * 1024;
        red_mb  = mapa_sc(red_mbar, p);
        hy_dst  = mapa_sc(smb + HYB_OFF * 4, p) + rank * 1024;
        hy_src  = smb + HYST_OFF * 4;
        hy_mb   = mapa_sc(hy_mbar, p);
    }

    float hy_r = 0.f, hz_r = 0.f, g_r = 0.f, e_r = 0.f, tI = 0.f;
    size_t row_base = 0;
    if (tid < 256) {
        g_r = gamma_v[k_own];
        e_r = eps_v[k_own];
        row_base = (size_t)(m_base + m_u) * T_LEN * NH + k_own;
        tI = g_tanhI[row_base];
    }

    __syncthreads();

    // --- GEMM1 weights -> registers as k-pair packed ulls (fully unrolled) ---
    ull wp[32];
    {
        const ull* wsrc = reinterpret_cast<const ull*>(sm + W_OFF + jg * WS + ks * 64);
        #pragma unroll
        for (int i = 0; i < 32; ++i) wp[i] = wsrc[i];
    }

    cluster_sync_();   // weights / zeroed hyb / armed mbars visible cluster-wide

    const ulonglong2* hb = reinterpret_cast<const ulonglong2*>(sm + HYB_OFF + ks * 256);
    const ull* w2p = reinterpret_cast<const ull*>(sm + W_OFF) + kp;   // stride 257 ull

    for (int t = 0; t < T_LEN; ++t) {
        // ---- wait hy delivery (phase t-1), re-arm next hy phase ----
        if (t) {
            mbar_wait(hy_mbar, (uint32_t)((t + 1) & 1));
            if (tid == 0 && t <= T_LEN - 2) mbar_expect(hy_mbar, 7168);
        }

        // ---- GEMM1: k-pair packed, register weights, broadcast hy loads ----
        {
            ull a0 = 0, a1 = 0, a2 = 0, a3 = 0;
            #pragma unroll
            for (int i = 0; i < 16; ++i) {
                ulonglong2 h0 = hb[i];
                ulonglong2 h1 = hb[16 + i];
                ulonglong2 h2 = hb[32 + i];
                ulonglong2 h3 = hb[48 + i];
                ffma2(a0, wp[2 * i], h0.x); ffma2(a0, wp[2 * i + 1], h0.y);
                ffma2(a1, wp[2 * i], h1.x); ffma2(a1, wp[2 * i + 1], h1.y);
                ffma2(a2, wp[2 * i], h2.x); ffma2(a2, wp[2 * i + 1], h2.y);
                ffma2(a3, wp[2 * i], h3.x); ffma2(a3, wp[2 * i + 1], h3.y);
            }
            float4 o;
            float lo, hi;
            unpack2(lo, hi, a0); o.x = lo + hi;
            unpack2(lo, hi, a1); o.y = lo + hi;
            unpack2(lo, hi, a2); o.z = lo + hi;
            unpack2(lo, hi, a3); o.w = lo + hi;
            *reinterpret_cast<float4*>(sm + STG_OFF + (ks * 64 + jg) * 4) = o;
        }
        __syncthreads();
        if (tid < 256) {                 // sum 8 partials + bias + tanh -> pd dup
            const int rj = tid >> 2, rm = tid & 3;
            float s = bias_s[rj];
            #pragma unroll
            for (int q = 0; q < 8; ++q) s += sm[STG_OFF + q * 256 + rj * 4 + rm];
            pd64[rj * 4 + rm] = pack2(tanhf(s));
        }
        __syncthreads();

        // ---- GEMM2: k-pair per thread, m-half split, dup-pre operands ----
        {
            ull c0 = 0, c1 = 0;          // {k0,k1} accum for m = 2mh, 2mh+1
            #pragma unroll 16
            for (int j = 0; j < 64; ++j) {
                ull w2 = w2p[j * 257];
                ulonglong2 pv = *reinterpret_cast<const ulonglong2*>(
                    pd64 + j * 4 + 2 * mh);
                ffma2(c0, w2, pv.x);
                ffma2(c1, w2, pv.y);
            }
            const int tgt = kp >> 5;
            const int off = (kp & 31) * 2;
            float* base = (tgt == (int)rank) ? (sm + RED_OFF + (int)rank * 256)
                                             : (sm + RDO_OFF + tgt * 256);
            *reinterpret_cast<ull*>(base + (2 * mh) * 64 + off)     = c0;
            *reinterpret_cast<ull*>(base + (2 * mh + 1) * 64 + off) = c1;
        }
        __syncthreads();                 // staging + self red complete

        // ---- 7 x 1KB red bulk copies ----
        if (issuer) {
            fence_async_();
            bulk_dsm(red_dst, red_src, 1024, red_mb);
        }

        // ---- owner update: wait red tx, re-arm, reduce, integrate ----
        if (tid < 256) {
            int tn = (t + 1 < T_LEN) ? (t + 1) : (T_LEN - 1);
            float tI_next = g_tanhI[row_base + (size_t)tn * NH];   // overlap wait

            mbar_wait(red_mbar, (uint32_t)(t & 1));
            if (tid == 0 && t + 1 < T_LEN) mbar_expect(red_mbar, 7168);

            float s = 0.f;
            #pragma unroll
            for (int src = 0; src < 8; ++src) s += sm[RED_OFF + src * 256 + tid];

            hz_r = hz_r + DT_C * (tI - s - g_r * hy_r - e_r * hz_r);
            hy_r = hy_r + DT_C * hz_r;
            tI = tI_next;

            sm[HYST_OFF + tid] = hy_r;                   // [m][kl] staging
            sm[HYB_OFF + (int)rank * 256 + tid] = hy_r;  // self hy block direct
        }
        __syncthreads();                 // hyst + self hy visible

        // ---- 7 x 1KB hy bulk copies first (critical path) ----
        if (t + 1 < T_LEN && issuer) {
            fence_async_();
            bulk_dsm(hy_dst, hy_src, 1024, hy_mb);
        }
        // ---- coalesced out_states: 64 threads, float4 each ----
        if (out_states && tid >= 320 && tid < 384) {
            const int q = tid - 320;
            const int m = q >> 4, c4 = q & 15;
            float4 v = *reinterpret_cast<const float4*>(sm + HYST_OFF + m * 64 + c4 * 4);
            *reinterpret_cast<float4*>(
                out_states + (size_t)(m_base + m) * T_LEN * NH +
                (size_t)t * NH + J0 + c4 * 4) = v;
        }
    }

    if (tid < 256 && out_hy)
        out_hy[(size_t)(m_base + m_u) * NH + k_own] = hy_r;

    cluster_sync_();   // keep smem alive until all peer traffic settles
}

// ---------------------------------------------------------------------------
extern "C" void kernel_launch(void* const* d_in, const int* in_sizes, int n_in,
                              void* d_out, int out_size) {
    const float* x    = (const float*)d_in[0];
    const float* x2h  = (const float*)d_in[1];
    const float* h2h  = (const float*)d_in[2];
    const float* bias = (const float*)d_in[3];
    const float* gam  = (const float*)d_in[4];
    const float* eps  = (const float*)d_in[5];
    float* out = (float*)d_out;

    const long long BTH = (long long)BSZ * T_LEN * NH;
    float* states = nullptr;
    float* hyout  = nullptr;
    if ((long long)out_size >= BTH) {
        states = out;
        if ((long long)out_size >= BTH + (long long)BSZ * NH) hyout = out + BTH;
    } else {
        hyout = out;
    }

    phase1_kernel<<<(BSZ * T_LEN) / 16, 256>>>(x, x2h);

    cudaFuncSetAttribute(rnn_kernel, cudaFuncAttributeMaxDynamicSharedMemorySize,
                         SMEM_BYTES);

    cudaLaunchConfig_t cfg = {};
    cfg.gridDim = dim3(128, 1, 1);
    cfg.blockDim = dim3(512, 1, 1);
    cfg.dynamicSmemBytes = SMEM_BYTES;
    cfg.stream = 0;
    cudaLaunchAttribute attrs[1];
    attrs[0].id = cudaLaunchAttributeClusterDimension;
    attrs[0].val.clusterDim.x = 8;
    attrs[0].val.clusterDim.y = 1;
    attrs[0].val.clusterDim.z = 1;
    cfg.attrs = attrs;
    cfg.numAttrs = 1;
    cudaLaunchKernelEx(&cfg, rnn_kernel, h2h, bias, gam, eps, states, hyout);
}